// round 14
// baseline (speedup 1.0000x reference)
#include <cuda_runtime.h>
#include <math.h>

#define NP 512
#define ND 3
#define NK 32
#define NT 10
#define NB 8
#define EPSF 1e-6f

#define NTAB 256
#define DRANGE 4.0f
#define TSCALE ((float)NTAB / DRANGE)
#define FMAGIC 8388608.0f                // 2^23

#define IPB 8                            // target i's per block (= warps per block)
#define PTPB (IPB * 32)                  // 256 threads
#define PAIR_BLOCKS (NB * (NP / IPB))    // 512 blocks

__device__ float    g_divpart[NB * NP];
__device__ unsigned g_count = 0;

__global__ void __launch_bounds__(PTPB, 4) fused_kernel(
    const float* __restrict__ t_in,
    const float* __restrict__ x,
    const float* __restrict__ mus,
    const float* __restrict__ nlg,
    const float* __restrict__ mus_t,
    const float* __restrict__ nlg_t,
    const float* __restrict__ W,
    const float* __restrict__ bias,
    const float* __restrict__ imp,
    float* __restrict__ out)
{
    __shared__ float4 s_kp[IPB][NK];     // per-warp private (mu, ig2, w, -) : 4 KB
    __shared__ float2 s_raw[NTAB];       // raw (fm, dfm) samples : 2 KB
    __shared__ float4 s_tab[NTAB];       // (fm, dfm, slope_fm, slope_dfm) : 4 KB
    __shared__ float4 s_pos[NP];         // positions : 8 KB
    __shared__ int    s_last;

    const int tid   = threadIdx.x;
    const int bid   = blockIdx.x;
    const int b     = bid >> 6;               // batch (bid / 64)
    const int ibase = (bid & 63) * IPB;       // i-chunk of 8
    const int warp  = tid >> 5;
    const int lane  = tid & 31;
    const unsigned m = 0xffffffffu;

    // ---- positions into smem (2 per thread; issued early) ----
    {
        const float* xb = x + b * (NP * ND);
#pragma unroll
        for (int h = 0; h < 2; h++) {
            const int p = tid + h * PTPB;
            float4 v;
            v.x = xb[p * 3 + 0]; v.y = xb[p * 3 + 1]; v.z = xb[p * 3 + 2]; v.w = 0.f;
            s_pos[p] = v;
        }
    }

    // ---- every warp redundantly computes the full weight set (lane = k) ----
    float cadd;
    {
        const int k = lane;
        const float t = t_in[0];
        float tr[NT];
        float ssum = 0.f;
#pragma unroll
        for (int q = 0; q < NT; q++) {
            float ig = __expf(nlg_t[q]);
            float df = t - mus_t[q];
            float v  = __expf(-df * df * ig * ig);
            tr[q] = v;
            ssum += v;
        }
        const float invs = 1.0f / (EPSF + ssum);

        float w = 0.f;
#pragma unroll
        for (int q = 0; q < NT; q++) w = fmaf(W[k * NT + q], tr[q], w);
        w *= invs;

        float vv = imp[k] * imp[k] * w;
#pragma unroll
        for (int o = 16; o; o >>= 1) vv += __shfl_xor_sync(m, vv, o);

        cadd = vv;
#pragma unroll
        for (int q = 0; q < NT; q++) cadd = fmaf(bias[q] * invs, tr[q], cadd);

        float ig = __expf(nlg[k]);
        float4 kp;
        kp.x = mus[k]; kp.y = ig * ig; kp.z = w; kp.w = 0.f;
        s_kp[warp][k] = kp;
    }
    __syncwarp();

    // ---- each thread builds one raw table entry (reads only own warp's kp copy) ----
    {
        const float dtab = (float)tid * (DRANGE / (float)NTAB);
        float S0 = 0.f, W0 = 0.f, SD = 0.f, SDW = 0.f;
#pragma unroll 8
        for (int k = 0; k < NK; k++) {
            const float4 kp = s_kp[warp][k];
            float diff = dtab - kp.x;
            float r  = __expf(-diff * diff * kp.y);
            float dr = -2.f * diff * kp.y * r;
            S0  += r;
            W0   = fmaf(r,  kp.z, W0);
            SD  += dr;
            SDW  = fmaf(dr, kp.z, SDW);
        }
        const float inv = 1.0f / (EPSF + S0);
        float2 e;
        e.x = fmaf(W0, inv, cadd);          // fm
        e.y = (SDW - W0 * SD * inv) * inv;  // dfm
        s_raw[tid] = e;
    }
    __syncthreads();

    // ---- slope-form quads (tail slope = 0: flat asymptote) ----
    {
        const float2 e0 = s_raw[tid];
        const float2 e1 = (tid < NTAB - 1) ? s_raw[tid + 1] : e0;
        float4 q;
        q.x = e0.x; q.y = e0.y; q.z = e1.x - e0.x; q.w = e1.y - e0.y;
        s_tab[tid] = q;
    }
    __syncthreads();

    // ---- pair loop: warp w -> target i ----
    const int i = ibase + warp;
    const float4 pi = s_pos[i];

    float fx = 0.f, fy = 0.f, fz = 0.f, dv = 0.f;

#pragma unroll 8
    for (int it = 0; it < NP / 32; it++) {
        const float4 pj = s_pos[it * 32 + lane];
        const float rx = pi.x - pj.x;
        const float ry = pi.y - pj.y;
        const float rz = pi.z - pj.z;
        float d2s = fmaf(rx, rx, fmaf(ry, ry, fmaf(rz, rz, EPSF)));
        float d;
        asm("sqrt.approx.ftz.f32 %0, %1;" : "=f"(d) : "f"(d2s));

        // float-magic floor: i0 = round(u - 0.5), frac = u - (float)i0  (all 4-cyc ops)
        const float u  = d * TSCALE;
        const float fm_ = fmaf(d, TSCALE, FMAGIC - 0.5f);   // (u - 0.5) + 2^23
        int i0 = __float_as_int(fm_) & 0xFFFF;
        i0 = min(i0, NTAB - 1);
        const float fru = __int_as_float(__float_as_int(fm_)) - FMAGIC; // ~(float)round(u-0.5)
        float frac = u - fru;

        const float4 q = s_tab[i0];
        float fm  = fmaf(frac, q.z, q.x);
        float dfm = fmaf(frac, q.w, q.y);

        fx = fmaf(rx, fm, fx);
        fy = fmaf(ry, fm, fy);
        fz = fmaf(rz, fm, fz);
        dv += fmaf(d, dfm, 3.f * fm);
    }

    // ---- warp reduction ----
#pragma unroll
    for (int o = 16; o; o >>= 1) {
        fx += __shfl_down_sync(m, fx, o);
        fy += __shfl_down_sync(m, fy, o);
        fz += __shfl_down_sync(m, fz, o);
        dv += __shfl_down_sync(m, dv, o);
    }
    if (lane == 0) {
        // subtract the diagonal contribution (identical arithmetic path -> cancels)
        float d0;
        asm("sqrt.approx.ftz.f32 %0, %1;" : "=f"(d0) : "f"(EPSF));
        const float u0  = d0 * TSCALE;
        const float fm0_ = fmaf(d0, TSCALE, FMAGIC - 0.5f);
        int i00 = __float_as_int(fm0_) & 0xFFFF;
        i00 = min(i00, NTAB - 1);
        const float fru0 = __int_as_float(__float_as_int(fm0_)) - FMAGIC;
        float fr0 = u0 - fru0;
        const float4 q0 = s_tab[i00];
        float fmv  = fmaf(fr0, q0.z, q0.x);
        float dfm0 = fmaf(fr0, q0.w, q0.y);
        dv -= fmaf(d0, dfm0, 3.f * fmv);

        float* fo = out + b * (NP * ND) + i * 3;
        fo[0] = fx; fo[1] = fy; fo[2] = fz;
        g_divpart[b * NP + i] = dv;
        __threadfence();
    }
    __syncthreads();

    if (tid == 0) {
        unsigned old = atomicInc(&g_count, PAIR_BLOCKS - 1);
        s_last = (old == PAIR_BLOCKS - 1) ? 1 : 0;
    }
    __syncthreads();

    // ---- last block: deterministic divergence reduction ----
    if (s_last) {
        __threadfence();
        const int bb = tid >> 5;   // warp -> batch (8 warps, 256 threads)
        const int l  = tid & 31;
        float v = 0.f;
#pragma unroll
        for (int c = 0; c < 16; c++)
            v += __ldcg(&g_divpart[bb * NP + l * 16 + c]);
#pragma unroll
        for (int o = 16; o; o >>= 1) v += __shfl_down_sync(m, v, o);
        if (l == 0) out[NB * NP * ND + bb] = -v;
    }
}

extern "C" void kernel_launch(void* const* d_in, const int* in_sizes, int n_in,
                              void* d_out, int out_size)
{
    const float* t_in  = (const float*)d_in[0];
    const float* x     = (const float*)d_in[1];
    const float* mus   = (const float*)d_in[2];
    const float* nlg   = (const float*)d_in[3];
    const float* mus_t = (const float*)d_in[4];
    const float* nlg_t = (const float*)d_in[5];
    const float* W     = (const float*)d_in[6];
    const float* bias  = (const float*)d_in[7];
    const float* imp   = (const float*)d_in[8];
    float* out = (float*)d_out;

    fused_kernel<<<PAIR_BLOCKS, PTPB>>>(t_in, x, mus, nlg, mus_t, nlg_t, W, bias, imp, out);
}

// round 15
// speedup vs baseline: 1.1217x; 1.1217x over previous
#include <cuda_runtime.h>
#include <math.h>

#define NP 512
#define ND 3
#define NK 32
#define NT 10
#define NB 8
#define EPSF 1e-6f

#define NTAB 256
#define DRANGE 4.0f
#define TSCALE ((float)NTAB / DRANGE)
#define FMAGIC 8388608.0f                // 2^23

#define IPB 8                            // target i's per block (= warps per block)
#define PTPB (IPB * 32)                  // 256 threads
#define PAIR_BLOCKS (NB * (NP / IPB))    // 512 blocks

__device__ float    g_divpart[NB * NP];
__device__ unsigned g_count = 0;

__global__ void __launch_bounds__(PTPB, 4) fused_kernel(
    const float* __restrict__ t_in,
    const float* __restrict__ x,
    const float* __restrict__ mus,
    const float* __restrict__ nlg,
    const float* __restrict__ mus_t,
    const float* __restrict__ nlg_t,
    const float* __restrict__ W,
    const float* __restrict__ bias,
    const float* __restrict__ imp,
    float* __restrict__ out)
{
    __shared__ float2 s_w2[NK];          // (w_k, k*w_k)
    __shared__ float  s_c[8];            // recurrence constants + cadd
    __shared__ float2 s_raw[NTAB];       // raw (fm, dfm) samples
    __shared__ float4 s_tab[NTAB];       // (fm, dfm, slope_fm, slope_dfm)
    __shared__ float4 s_pos[NP];         // positions
    __shared__ int    s_last;

    const int tid   = threadIdx.x;
    const int bid   = blockIdx.x;
    const int b     = bid >> 6;               // batch (bid / 64)
    const int ibase = (bid & 63) * IPB;       // i-chunk of 8
    const int warp  = tid >> 5;
    const int lane  = tid & 31;
    const unsigned m = 0xffffffffu;

    // ---- positions into smem (2 per thread; issued early) ----
    {
        const float* xb = x + b * (NP * ND);
#pragma unroll
        for (int h = 0; h < 2; h++) {
            const int p = tid + h * PTPB;
            float4 v;
            v.x = xb[p * 3 + 0]; v.y = xb[p * 3 + 1]; v.z = xb[p * 3 + 2]; v.w = 0.f;
            s_pos[p] = v;
        }
    }

    // ---- warp 0 only: lane-parallel weight phase ----
    if (warp == 0) {
        const float t = t_in[0];
        float my = 0.f;                     // lane q < NT holds raw tr[q]
        if (lane < NT) {
            float ig = __expf(nlg_t[lane]);
            float df = t - mus_t[lane];
            my = __expf(-df * df * ig * ig);
        }
        float ssum = my;
#pragma unroll
        for (int o = 16; o; o >>= 1) ssum += __shfl_xor_sync(m, ssum, o);
        const float invs = 1.0f / (EPSF + ssum);

        // each lane k builds w_k from broadcast tr values
        float w = 0.f;
#pragma unroll
        for (int q = 0; q < NT; q++) {
            float trq = __shfl_sync(m, my, q) * invs;
            w = fmaf(W[lane * NT + q], trq, w);
        }

        // importance + bias contributions to cadd (reduced across lanes)
        float vv = imp[lane] * imp[lane] * w;
        if (lane < NT) vv = fmaf(bias[lane] * invs, my, vv);
#pragma unroll
        for (int o = 16; o; o >>= 1) vv += __shfl_xor_sync(m, vv, o);

        s_w2[lane] = make_float2(w, (float)lane * w);

        if (lane == 0) {
            const float L = 1.4426950408889634074f;   // log2(e)
            float gg = __expf(nlg[0]); gg *= gg;
            const float mu0 = mus[0];
            const float dm  = mus[1] - mus[0];
            s_c[0] = -gg * L;                 // c0 : arg0 = c0*e^2
            s_c[1] = 2.f * gg * dm * L;       // c1
            s_c[2] = -gg * dm * dm * L;       // c2 : argP = c1*e + c2
            s_c[3] = exp2f(-2.f * gg * dm * dm * L);  // Q
            s_c[4] = -2.f * gg;               // alpha = c4 * e
            s_c[5] = 2.f * gg * dm;           // delta
            s_c[6] = mu0;
            s_c[7] = vv;                      // cadd
        }
    }
    __syncthreads();

    // ---- each thread builds one raw table entry via multiplicative recurrence ----
    {
        const float dtab = (float)tid * (DRANGE / (float)NTAB);
        const float e = dtab - s_c[6];
        float rbf, P;
        {
            float a0 = s_c[0] * e * e;
            asm("ex2.approx.ftz.f32 %0, %1;" : "=f"(rbf) : "f"(a0));
            float aP = fmaf(s_c[1], e, s_c[2]);
            asm("ex2.approx.ftz.f32 %0, %1;" : "=f"(P) : "f"(aP));
        }
        const float Q = s_c[3];
        float M = P;
        float S0 = 0.f, S1 = 0.f, W0 = 0.f, W1 = 0.f, kf = 0.f;
#pragma unroll 8
        for (int k = 0; k < NK; k++) {
            const float2 wk = s_w2[k];        // broadcast LDS (conflict-free)
            S0 += rbf;
            S1 = fmaf(rbf, kf, S1);
            W0 = fmaf(rbf, wk.x, W0);
            W1 = fmaf(rbf, wk.y, W1);
            kf += 1.f;
            rbf *= M;
            M   *= Q;
        }
        const float inv = 1.0f / (EPSF + S0);
        const float alpha = s_c[4] * e;
        const float delta = s_c[5];
        const float swi = W0 * inv;
        const float sd  = fmaf(delta, S1, alpha * S0);
        const float sdw = fmaf(delta, W1, alpha * W0);
        float2 entry;
        entry.x = swi + s_c[7];                   // fm
        entry.y = inv * fmaf(-swi, sd, sdw);      // dfm
        s_raw[tid] = entry;
    }
    __syncthreads();

    // ---- slope-form quads (tail slope = 0: flat asymptote) ----
    {
        const float2 e0 = s_raw[tid];
        const float2 e1 = (tid < NTAB - 1) ? s_raw[tid + 1] : e0;
        float4 q;
        q.x = e0.x; q.y = e0.y; q.z = e1.x - e0.x; q.w = e1.y - e0.y;
        s_tab[tid] = q;
    }
    __syncthreads();

    // ---- pair loop: warp w -> target i ----
    const int i = ibase + warp;
    const float4 pi = s_pos[i];

    float fx = 0.f, fy = 0.f, fz = 0.f, dv = 0.f;

#pragma unroll 8
    for (int it = 0; it < NP / 32; it++) {
        const float4 pj = s_pos[it * 32 + lane];
        const float rx = pi.x - pj.x;
        const float ry = pi.y - pj.y;
        const float rz = pi.z - pj.z;
        float d2s = fmaf(rx, rx, fmaf(ry, ry, fmaf(rz, rz, EPSF)));
        float d;
        asm("sqrt.approx.ftz.f32 %0, %1;" : "=f"(d) : "f"(d2s));

        const float u  = d * TSCALE;
        const float fm_ = fmaf(d, TSCALE, FMAGIC - 0.5f);
        int i0 = __float_as_int(fm_) & 0xFFFF;
        i0 = min(i0, NTAB - 1);
        const float fru = __int_as_float(__float_as_int(fm_)) - FMAGIC;
        float frac = u - fru;

        const float4 q = s_tab[i0];
        float fm  = fmaf(frac, q.z, q.x);
        float dfm = fmaf(frac, q.w, q.y);

        fx = fmaf(rx, fm, fx);
        fy = fmaf(ry, fm, fy);
        fz = fmaf(rz, fm, fz);
        dv += fmaf(d, dfm, 3.f * fm);
    }

    // ---- warp reduction ----
#pragma unroll
    for (int o = 16; o; o >>= 1) {
        fx += __shfl_down_sync(m, fx, o);
        fy += __shfl_down_sync(m, fy, o);
        fz += __shfl_down_sync(m, fz, o);
        dv += __shfl_down_sync(m, dv, o);
    }
    if (lane == 0) {
        // subtract the diagonal contribution (identical arithmetic path -> cancels)
        float d0;
        asm("sqrt.approx.ftz.f32 %0, %1;" : "=f"(d0) : "f"(EPSF));
        const float u0  = d0 * TSCALE;
        const float fm0_ = fmaf(d0, TSCALE, FMAGIC - 0.5f);
        int i00 = __float_as_int(fm0_) & 0xFFFF;
        i00 = min(i00, NTAB - 1);
        const float fru0 = __int_as_float(__float_as_int(fm0_)) - FMAGIC;
        float fr0 = u0 - fru0;
        const float4 q0 = s_tab[i00];
        float fmv  = fmaf(fr0, q0.z, q0.x);
        float dfm0 = fmaf(fr0, q0.w, q0.y);
        dv -= fmaf(d0, dfm0, 3.f * fmv);

        float* fo = out + b * (NP * ND) + i * 3;
        fo[0] = fx; fo[1] = fy; fo[2] = fz;
        g_divpart[b * NP + i] = dv;
        __threadfence();
    }
    __syncthreads();

    if (tid == 0) {
        unsigned old = atomicInc(&g_count, PAIR_BLOCKS - 1);
        s_last = (old == PAIR_BLOCKS - 1) ? 1 : 0;
    }
    __syncthreads();

    // ---- last block: deterministic divergence reduction ----
    if (s_last) {
        __threadfence();
        const int bb = tid >> 5;   // warp -> batch (8 warps, 256 threads)
        const int l  = tid & 31;
        float v = 0.f;
#pragma unroll
        for (int c = 0; c < 16; c++)
            v += __ldcg(&g_divpart[bb * NP + l * 16 + c]);
#pragma unroll
        for (int o = 16; o; o >>= 1) v += __shfl_down_sync(m, v, o);
        if (l == 0) out[NB * NP * ND + bb] = -v;
    }
}

extern "C" void kernel_launch(void* const* d_in, const int* in_sizes, int n_in,
                              void* d_out, int out_size)
{
    const float* t_in  = (const float*)d_in[0];
    const float* x     = (const float*)d_in[1];
    const float* mus   = (const float*)d_in[2];
    const float* nlg   = (const float*)d_in[3];
    const float* mus_t = (const float*)d_in[4];
    const float* nlg_t = (const float*)d_in[5];
    const float* W     = (const float*)d_in[6];
    const float* bias  = (const float*)d_in[7];
    const float* imp   = (const float*)d_in[8];
    float* out = (float*)d_out;

    fused_kernel<<<PAIR_BLOCKS, PTPB>>>(t_in, x, mus, nlg, mus_t, nlg_t, W, bias, imp, out);
}